// round 6
// baseline (speedup 1.0000x reference)
#include <cuda_runtime.h>

// Problem constants (fixed by the reference)
#define NN 50000      // nodes
#define EE 800000     // edges
#define GG 32         // graphs
#define CC 16         // classes
#define NEG_SLOPE 0.2f
#define BN_EPS 1e-5f

// ---------------------------------------------------------------------------
// Scratch (static device globals; no allocation allowed)
// ---------------------------------------------------------------------------
__device__ float g_buf0[NN * 128];   // layer activations (ping)
__device__ float g_buf1[NN * 128];   // layer activations (pong)
__device__ float g_z[NN * 128];      // z = h @ W for current layer
__device__ float g_score[EE * 2];    // per-edge per-head score, then exp(score-max)
__device__ float g_denom[NN * 2];    // softmax denominators per dst,head
__device__ int   g_maxi[NN * 2];     // ordered-int encoded segment max per dst,head
__device__ float g_outf[NN * 32];    // final layer output [N,2,16]
__device__ float g_pooled[GG * CC];  // graph-pooled logits

// ---------------------------------------------------------------------------
// Helpers
// ---------------------------------------------------------------------------
__device__ __forceinline__ int f2o(float f) {           // order-preserving float->int
    int i = __float_as_int(f);
    return i >= 0 ? i : (i ^ 0x7fffffff);
}
__device__ __forceinline__ float o2f(int i) {
    return __int_as_float(i >= 0 ? i : (i ^ 0x7fffffff));
}
__device__ __forceinline__ float lrelu(float x) { return x > 0.f ? x : NEG_SLOPE * x; }

// ---------------------------------------------------------------------------
// Tiled SGEMM: Z[nrows, NC] = act(A[nrows,128]) @ W[128, NC]
// 128 rows per block, 256 threads, K chunked by 32 through shared memory.
// NC=128 (CPT=8) for hidden layers, NC=32 (CPT=2) for the final projection.
// relu_in != 0 applies ReLU to A while loading (layer activation fusion).
// ---------------------------------------------------------------------------
template <int NC, int CPT>
__global__ void __launch_bounds__(256)
gemm_k128(const float* __restrict__ A, const float* __restrict__ W,
          float* __restrict__ Z, int nrows, int relu_in)
{
    __shared__ float hs[128][33];     // padded to kill bank conflicts on a-loads
    __shared__ float Ws[32][NC];

    const int t  = threadIdx.x;
    const int tx = t & 15;            // column group
    const int ty = t >> 4;            // row group
    const int rowBase = blockIdx.x * 128;

    float acc[8][CPT];
#pragma unroll
    for (int i = 0; i < 8; i++)
#pragma unroll
        for (int j = 0; j < CPT; j++) acc[i][j] = 0.f;

#pragma unroll
    for (int kc = 0; kc < 4; kc++) {
        // --- stage A chunk: rows [rowBase, rowBase+128), cols [kc*32, kc*32+32)
#pragma unroll
        for (int q = 0; q < 4; q++) {
            int idx = t + q * 256;          // float4 index in [0,1024)
            int e   = idx * 4;
            int r   = e >> 5;               // 0..127
            int c   = e & 31;               // 0,4,...,28
            int gr  = rowBase + r;
            float4 v = make_float4(0.f, 0.f, 0.f, 0.f);
            if (gr < nrows)
                v = *reinterpret_cast<const float4*>(A + (size_t)gr * 128 + kc * 32 + c);
            if (relu_in) {
                v.x = fmaxf(v.x, 0.f); v.y = fmaxf(v.y, 0.f);
                v.z = fmaxf(v.z, 0.f); v.w = fmaxf(v.w, 0.f);
            }
            hs[r][c + 0] = v.x; hs[r][c + 1] = v.y;
            hs[r][c + 2] = v.z; hs[r][c + 3] = v.w;
        }
        // --- stage W chunk: rows [kc*32, kc*32+32), all NC cols
        constexpr int WV = (32 * NC) / 4;
#pragma unroll
        for (int idx = t; idx < WV; idx += 256) {
            int e = idx * 4;
            int r = e / NC;
            int c = e % NC;
            float4 v = *reinterpret_cast<const float4*>(W + (size_t)(kc * 32 + r) * NC + c);
            *reinterpret_cast<float4*>(&Ws[r][c]) = v;
        }
        __syncthreads();

#pragma unroll
        for (int k = 0; k < 32; k++) {
            float a[8], b[CPT];
#pragma unroll
            for (int i = 0; i < 8; i++) a[i] = hs[ty + 16 * i][k];
#pragma unroll
            for (int j = 0; j < CPT; j++) b[j] = Ws[k][tx + 16 * j];
#pragma unroll
            for (int i = 0; i < 8; i++)
#pragma unroll
                for (int j = 0; j < CPT; j++)
                    acc[i][j] = fmaf(a[i], b[j], acc[i][j]);
        }
        __syncthreads();
    }

#pragma unroll
    for (int i = 0; i < 8; i++) {
        int gr = rowBase + ty + 16 * i;
        if (gr < nrows) {
#pragma unroll
            for (int j = 0; j < CPT; j++)
                Z[(size_t)gr * NC + tx + 16 * j] = acc[i][j];
        }
    }
}

// ---------------------------------------------------------------------------
// Per-layer init: zero accumulation buffer, zero denominators, -inf segment max
// ---------------------------------------------------------------------------
__global__ void init_k(float* __restrict__ out, int nout, int zero_pooled)
{
    int idx = blockIdx.x * blockDim.x + threadIdx.x;
    if (idx < nout) out[idx] = 0.f;
    if (idx < NN * 2) { g_denom[idx] = 0.f; g_maxi[idx] = (int)0x80000000; }
    if (zero_pooled && idx < GG * CC) g_pooled[idx] = 0.f;
}

// ---------------------------------------------------------------------------
// Hidden layers (D=64, H=2): one warp per edge.
// Lanes 0..15 = head 0 dims, lanes 16..31 = head 1 dims (4 dims each).
// ---------------------------------------------------------------------------
__global__ void __launch_bounds__(256)
edge_score_128(const float* __restrict__ z, const int* __restrict__ src,
               const int* __restrict__ dst, const float* __restrict__ attn)
{
    int e = blockIdx.x * 8 + (threadIdx.x >> 5);
    if (e >= EE) return;
    int lane = threadIdx.x & 31;
    int s = __ldg(src + e), d = __ldg(dst + e);

    float4 zs = *reinterpret_cast<const float4*>(z + (size_t)s * 128 + lane * 4);
    float4 zd = *reinterpret_cast<const float4*>(z + (size_t)d * 128 + lane * 4);
    float4 at = *reinterpret_cast<const float4*>(attn + lane * 4);   // attn flat [128]

    float ex = lrelu(zs.x + zd.x);
    float ey = lrelu(zs.y + zd.y);
    float ez = lrelu(zs.z + zd.z);
    float ew = lrelu(zs.w + zd.w);
    float p = ex * at.x + ey * at.y + ez * at.z + ew * at.w;

    p += __shfl_xor_sync(0xffffffffu, p, 8);
    p += __shfl_xor_sync(0xffffffffu, p, 4);
    p += __shfl_xor_sync(0xffffffffu, p, 2);
    p += __shfl_xor_sync(0xffffffffu, p, 1);

    if ((lane & 15) == 0) {
        int h = lane >> 4;
        g_score[e * 2 + h] = p;
        atomicMax(&g_maxi[d * 2 + h], f2o(p));
    }
}

// exp(score - max) + denominator accumulation (shared by all layers)
__global__ void edge_exp(const int* __restrict__ dst)
{
    int idx = blockIdx.x * blockDim.x + threadIdx.x;
    if (idx >= EE * 2) return;
    int e = idx >> 1, h = idx & 1;
    int d = __ldg(dst + e);
    float m = o2f(g_maxi[d * 2 + h]);
    float a = __expf(g_score[idx] - m);
    g_score[idx] = a;
    atomicAdd(&g_denom[d * 2 + h], a);
}

__global__ void __launch_bounds__(256)
edge_aggr_128(const float* __restrict__ z, const int* __restrict__ src,
              const int* __restrict__ dst, float* __restrict__ out)
{
    int e = blockIdx.x * 8 + (threadIdx.x >> 5);
    if (e >= EE) return;
    int lane = threadIdx.x & 31;
    int s = __ldg(src + e), d = __ldg(dst + e);
    int h = lane >> 4;

    float den = g_denom[d * 2 + h];
    float alpha = g_score[e * 2 + h] / (den == 0.f ? 1.f : den);

    float4 zs = *reinterpret_cast<const float4*>(z + (size_t)s * 128 + lane * 4);
    float* o = out + (size_t)d * 128 + lane * 4;
    atomicAdd(o + 0, zs.x * alpha);
    atomicAdd(o + 1, zs.y * alpha);
    atomicAdd(o + 2, zs.z * alpha);
    atomicAdd(o + 3, zs.w * alpha);
}

// ---------------------------------------------------------------------------
// Final layer (C=16, H=2): one thread per (edge, head)
// ---------------------------------------------------------------------------
__global__ void edge_score_f(const float* __restrict__ z, const int* __restrict__ src,
                             const int* __restrict__ dst, const float* __restrict__ attnf)
{
    int idx = blockIdx.x * blockDim.x + threadIdx.x;
    if (idx >= EE * 2) return;
    int e = idx >> 1, h = idx & 1;
    int s = __ldg(src + e), d = __ldg(dst + e);

    const float4* zs = reinterpret_cast<const float4*>(z + (size_t)s * 32 + h * 16);
    const float4* zd = reinterpret_cast<const float4*>(z + (size_t)d * 32 + h * 16);
    const float4* at = reinterpret_cast<const float4*>(attnf + h * 16);

    float p = 0.f;
#pragma unroll
    for (int q = 0; q < 4; q++) {
        float4 a = zs[q], b = zd[q], w = at[q];
        p += lrelu(a.x + b.x) * w.x;
        p += lrelu(a.y + b.y) * w.y;
        p += lrelu(a.z + b.z) * w.z;
        p += lrelu(a.w + b.w) * w.w;
    }
    g_score[idx] = p;
    atomicMax(&g_maxi[d * 2 + h], f2o(p));
}

__global__ void edge_aggr_f(const float* __restrict__ z, const int* __restrict__ src,
                            const int* __restrict__ dst, float* __restrict__ outf)
{
    int idx = blockIdx.x * blockDim.x + threadIdx.x;
    if (idx >= EE * 2) return;
    int e = idx >> 1, h = idx & 1;
    int s = __ldg(src + e), d = __ldg(dst + e);

    float den = g_denom[d * 2 + h];
    float alpha = g_score[idx] / (den == 0.f ? 1.f : den);

    const float4* zs = reinterpret_cast<const float4*>(z + (size_t)s * 32 + h * 16);
    float* o = outf + (size_t)d * 32 + h * 16;
#pragma unroll
    for (int q = 0; q < 4; q++) {
        float4 v = zs[q];
        atomicAdd(o + q * 4 + 0, v.x * alpha);
        atomicAdd(o + q * 4 + 1, v.y * alpha);
        atomicAdd(o + q * 4 + 2, v.z * alpha);
        atomicAdd(o + q * 4 + 3, v.w * alpha);
    }
}

// Mean over heads + graph pooling (segment_sum by node_graph)
__global__ void pool_k(const float* __restrict__ outf, const int* __restrict__ ng)
{
    int idx = blockIdx.x * blockDim.x + threadIdx.x;
    if (idx >= NN * CC) return;
    int n = idx >> 4, c = idx & 15;
    float v = 0.5f * (outf[n * 32 + c] + outf[n * 32 + 16 + c]);
    atomicAdd(&g_pooled[__ldg(ng + n) * CC + c], v);
}

// ---------------------------------------------------------------------------
// Tiny MLP head: lin -> batchnorm(training stats) -> relu -> lin -> log_softmax
// Single block, 512 threads = (32 graphs x 16 classes).
// ---------------------------------------------------------------------------
__global__ void __launch_bounds__(512)
mlp_k(const float* __restrict__ w1, const float* __restrict__ gamma,
      const float* __restrict__ beta, const float* __restrict__ w2,
      float* __restrict__ out)
{
    __shared__ float P[GG][CC], H1[GG][CC], R[GG][CC], O[GG][CC];
    __shared__ float mu[CC], iv[CC];
    __shared__ float rm[GG], rl[GG];

    int t = threadIdx.x;
    int i = t >> 4, j = t & 15;

    P[i][j] = g_pooled[t];
    __syncthreads();

    float acc = 0.f;
#pragma unroll
    for (int k = 0; k < CC; k++) acc += P[i][k] * w1[k * CC + j];
    H1[i][j] = acc;
    __syncthreads();

    if (t < CC) {
        float m = 0.f;
        for (int r = 0; r < GG; r++) m += H1[r][t];
        m *= (1.f / GG);
        float v = 0.f;
        for (int r = 0; r < GG; r++) { float d = H1[r][t] - m; v += d * d; }
        v *= (1.f / GG);
        mu[t] = m;
        iv[t] = rsqrtf(v + BN_EPS);
    }
    __syncthreads();

    float hn = (H1[i][j] - mu[j]) * iv[j] * gamma[j] + beta[j];
    R[i][j] = fmaxf(hn, 0.f);
    __syncthreads();

    acc = 0.f;
#pragma unroll
    for (int k = 0; k < CC; k++) acc += R[i][k] * w2[k * CC + j];
    O[i][j] = acc;
    __syncthreads();

    if (j == 0) {
        float m = -1e30f;
        for (int k = 0; k < CC; k++) m = fmaxf(m, O[i][k]);
        float s = 0.f;
        for (int k = 0; k < CC; k++) s += __expf(O[i][k] - m);
        rm[i] = m;
        rl[i] = logf(s);
    }
    __syncthreads();

    out[t] = O[i][j] - rm[i] - rl[i];
}

// ---------------------------------------------------------------------------
// Host launch sequence (graph-capturable; kernel launches only)
// ---------------------------------------------------------------------------
extern "C" void kernel_launch(void* const* d_in, const int* in_sizes, int n_in,
                              void* d_out, int out_size)
{
    const float* feat  = (const float*)d_in[0];
    const float* W0    = (const float*)d_in[1];
    const float* attn0 = (const float*)d_in[2];
    const float* W1    = (const float*)d_in[3];
    const float* attn1 = (const float*)d_in[4];
    const float* W2    = (const float*)d_in[5];
    const float* attn2 = (const float*)d_in[6];
    const float* Wf    = (const float*)d_in[7];
    const float* attnf = (const float*)d_in[8];
    const float* mw1   = (const float*)d_in[9];
    const float* gam   = (const float*)d_in[10];
    const float* bet   = (const float*)d_in[11];
    const float* mw2   = (const float*)d_in[12];
    const int*   src   = (const int*)d_in[13];
    const int*   dst   = (const int*)d_in[14];
    const int*   ng    = (const int*)d_in[15];

    float *buf0, *buf1, *zbuf, *outf;
    cudaGetSymbolAddress((void**)&buf0, g_buf0);
    cudaGetSymbolAddress((void**)&buf1, g_buf1);
    cudaGetSymbolAddress((void**)&zbuf, g_z);
    cudaGetSymbolAddress((void**)&outf, g_outf);

    const int GEMM_BLOCKS = (NN + 127) / 128;          // 391
    const int EW_BLOCKS   = (EE + 7) / 8;              // warp-per-edge: 100000
    const int ET_BLOCKS   = (EE * 2 + 255) / 256;      // thread-per-(edge,head): 6250
    const int INIT_BLOCKS = (NN * 128 + 255) / 256;    // 25000
    const int INITF_BLOCKS= (NN * 32 + 255) / 256;     // 6250 (covers NN*2 too)
    const int POOL_BLOCKS = (NN * CC + 255) / 256;     // 3125

    // ---- layer 0: feat -> buf0
    gemm_k128<128, 8><<<GEMM_BLOCKS, 256>>>(feat, W0, zbuf, NN, 0);
    init_k<<<INIT_BLOCKS, 256>>>(buf0, NN * 128, 0);
    edge_score_128<<<EW_BLOCKS, 256>>>(zbuf, src, dst, attn0);
    edge_exp<<<ET_BLOCKS, 256>>>(dst);
    edge_aggr_128<<<EW_BLOCKS, 256>>>(zbuf, src, dst, buf0);

    // ---- layer 1: relu(buf0) -> buf1
    gemm_k128<128, 8><<<GEMM_BLOCKS, 256>>>(buf0, W1, zbuf, NN, 1);
    init_k<<<INIT_BLOCKS, 256>>>(buf1, NN * 128, 0);
    edge_score_128<<<EW_BLOCKS, 256>>>(zbuf, src, dst, attn1);
    edge_exp<<<ET_BLOCKS, 256>>>(dst);
    edge_aggr_128<<<EW_BLOCKS, 256>>>(zbuf, src, dst, buf1);

    // ---- layer 2: relu(buf1) -> buf0
    gemm_k128<128, 8><<<GEMM_BLOCKS, 256>>>(buf1, W2, zbuf, NN, 1);
    init_k<<<INIT_BLOCKS, 256>>>(buf0, NN * 128, 0);
    edge_score_128<<<EW_BLOCKS, 256>>>(zbuf, src, dst, attn2);
    edge_exp<<<ET_BLOCKS, 256>>>(dst);
    edge_aggr_128<<<EW_BLOCKS, 256>>>(zbuf, src, dst, buf0);

    // ---- final GAT layer: relu(buf0) @ Wf -> zf [N,32]; aggregate -> outf
    gemm_k128<32, 2><<<GEMM_BLOCKS, 256>>>(buf0, Wf, zbuf, NN, 1);
    init_k<<<INITF_BLOCKS, 256>>>(outf, NN * 32, 1);
    edge_score_f<<<ET_BLOCKS, 256>>>(zbuf, src, dst, attnf);
    edge_exp<<<ET_BLOCKS, 256>>>(dst);
    edge_aggr_f<<<ET_BLOCKS, 256>>>(zbuf, src, dst, outf);

    // ---- head: mean over heads, graph pooling, MLP+BN+log_softmax
    pool_k<<<POOL_BLOCKS, 256>>>(outf, ng);
    mlp_k<<<1, 512>>>(mw1, gam, bet, mw2, (float*)d_out);

    (void)in_sizes; (void)n_in; (void)out_size;
}

// round 7
// speedup vs baseline: 1.5061x; 1.5061x over previous
#include <cuda_runtime.h>

// Problem constants (fixed by the reference)
#define NN 50000      // nodes
#define EE 800000     // edges
#define GG 32         // graphs
#define CC 16         // classes
#define NEG_SLOPE 0.2f
#define BN_EPS 1e-5f

// ---------------------------------------------------------------------------
// Scratch (static device globals; no allocation allowed)
// ---------------------------------------------------------------------------
__device__ float g_buf0[NN * 128];   // layer activations (ping)
__device__ float g_buf1[NN * 128];   // layer activations (pong)
__device__ float g_z[NN * 128];      // z = h @ W for current layer
__device__ float g_score[EE * 2];    // per-edge per-head score, then exp(score-max)
__device__ float g_denom[NN * 2];    // softmax denominators per dst,head
__device__ int   g_maxi[NN * 2];     // ordered-int encoded segment max per dst,head
__device__ float g_outf[NN * 32];    // final layer output [N,2,16]
__device__ float g_pooled[GG * CC];  // graph-pooled logits

// ---------------------------------------------------------------------------
// Helpers
// ---------------------------------------------------------------------------
__device__ __forceinline__ int f2o(float f) {           // order-preserving float->int
    int i = __float_as_int(f);
    return i >= 0 ? i : (i ^ 0x7fffffff);
}
__device__ __forceinline__ float o2f(int i) {
    return __int_as_float(i >= 0 ? i : (i ^ 0x7fffffff));
}
__device__ __forceinline__ float lrelu(float x) { return x > 0.f ? x : NEG_SLOPE * x; }

// ---------------------------------------------------------------------------
// Tiled SGEMM: Z[nrows, NC] = act(A[nrows,128]) @ W[128, NC]
// 128 rows per block, 256 threads, K chunked by 32 through shared memory.
// NC=128 (CPT=8) for hidden layers, NC=32 (CPT=2) for the final projection.
// relu_in != 0 applies ReLU to A while loading (layer activation fusion).
// ---------------------------------------------------------------------------
template <int NC, int CPT>
__global__ void __launch_bounds__(256)
gemm_k128(const float* __restrict__ A, const float* __restrict__ W,
          float* __restrict__ Z, int nrows, int relu_in)
{
    __shared__ float hs[128][33];     // padded to kill bank conflicts on a-loads
    __shared__ float Ws[32][NC];

    const int t  = threadIdx.x;
    const int tx = t & 15;            // column group
    const int ty = t >> 4;            // row group
    const int rowBase = blockIdx.x * 128;

    float acc[8][CPT];
#pragma unroll
    for (int i = 0; i < 8; i++)
#pragma unroll
        for (int j = 0; j < CPT; j++) acc[i][j] = 0.f;

#pragma unroll
    for (int kc = 0; kc < 4; kc++) {
        // --- stage A chunk: rows [rowBase, rowBase+128), cols [kc*32, kc*32+32)
#pragma unroll
        for (int q = 0; q < 4; q++) {
            int idx = t + q * 256;          // float4 index in [0,1024)
            int e   = idx * 4;
            int r   = e >> 5;               // 0..127
            int c   = e & 31;               // 0,4,...,28
            int gr  = rowBase + r;
            float4 v = make_float4(0.f, 0.f, 0.f, 0.f);
            if (gr < nrows)
                v = *reinterpret_cast<const float4*>(A + (size_t)gr * 128 + kc * 32 + c);
            if (relu_in) {
                v.x = fmaxf(v.x, 0.f); v.y = fmaxf(v.y, 0.f);
                v.z = fmaxf(v.z, 0.f); v.w = fmaxf(v.w, 0.f);
            }
            hs[r][c + 0] = v.x; hs[r][c + 1] = v.y;
            hs[r][c + 2] = v.z; hs[r][c + 3] = v.w;
        }
        // --- stage W chunk: rows [kc*32, kc*32+32), all NC cols
        constexpr int WV = (32 * NC) / 4;
#pragma unroll
        for (int idx = t; idx < WV; idx += 256) {
            int e = idx * 4;
            int r = e / NC;
            int c = e % NC;
            float4 v = *reinterpret_cast<const float4*>(W + (size_t)(kc * 32 + r) * NC + c);
            *reinterpret_cast<float4*>(&Ws[r][c]) = v;
        }
        __syncthreads();

#pragma unroll
        for (int k = 0; k < 32; k++) {
            float a[8], b[CPT];
#pragma unroll
            for (int i = 0; i < 8; i++) a[i] = hs[ty + 16 * i][k];
#pragma unroll
            for (int j = 0; j < CPT; j++) b[j] = Ws[k][tx + 16 * j];
#pragma unroll
            for (int i = 0; i < 8; i++)
#pragma unroll
                for (int j = 0; j < CPT; j++)
                    acc[i][j] = fmaf(a[i], b[j], acc[i][j]);
        }
        __syncthreads();
    }

#pragma unroll
    for (int i = 0; i < 8; i++) {
        int gr = rowBase + ty + 16 * i;
        if (gr < nrows) {
#pragma unroll
            for (int j = 0; j < CPT; j++)
                Z[(size_t)gr * NC + tx + 16 * j] = acc[i][j];
        }
    }
}

// ---------------------------------------------------------------------------
// Per-layer init: zero accumulation buffer, zero denominators, -inf segment max
// ---------------------------------------------------------------------------
__global__ void init_k(float* __restrict__ out, int nout, int zero_pooled)
{
    int idx = blockIdx.x * blockDim.x + threadIdx.x;
    if (idx < nout) out[idx] = 0.f;
    if (idx < NN * 2) { g_denom[idx] = 0.f; g_maxi[idx] = (int)0x80000000; }
    if (zero_pooled && idx < GG * CC) g_pooled[idx] = 0.f;
}

// ---------------------------------------------------------------------------
// Hidden layers (D=64, H=2): one warp per edge.
// Lanes 0..15 = head 0 dims, lanes 16..31 = head 1 dims (4 dims each).
// ---------------------------------------------------------------------------
__global__ void __launch_bounds__(256)
edge_score_128(const float* __restrict__ z, const int* __restrict__ src,
               const int* __restrict__ dst, const float* __restrict__ attn)
{
    int e = blockIdx.x * 8 + (threadIdx.x >> 5);
    if (e >= EE) return;
    int lane = threadIdx.x & 31;
    int s = __ldg(src + e), d = __ldg(dst + e);

    float4 zs = *reinterpret_cast<const float4*>(z + (size_t)s * 128 + lane * 4);
    float4 zd = *reinterpret_cast<const float4*>(z + (size_t)d * 128 + lane * 4);
    float4 at = *reinterpret_cast<const float4*>(attn + lane * 4);   // attn flat [128]

    float ex = lrelu(zs.x + zd.x);
    float ey = lrelu(zs.y + zd.y);
    float ez = lrelu(zs.z + zd.z);
    float ew = lrelu(zs.w + zd.w);
    float p = ex * at.x + ey * at.y + ez * at.z + ew * at.w;

    p += __shfl_xor_sync(0xffffffffu, p, 8);
    p += __shfl_xor_sync(0xffffffffu, p, 4);
    p += __shfl_xor_sync(0xffffffffu, p, 2);
    p += __shfl_xor_sync(0xffffffffu, p, 1);

    if ((lane & 15) == 0) {
        int h = lane >> 4;
        g_score[e * 2 + h] = p;
        atomicMax(&g_maxi[d * 2 + h], f2o(p));
    }
}

// exp(score - max) + denominator accumulation (shared by all layers)
__global__ void edge_exp(const int* __restrict__ dst)
{
    int idx = blockIdx.x * blockDim.x + threadIdx.x;
    if (idx >= EE * 2) return;
    int e = idx >> 1, h = idx & 1;
    int d = __ldg(dst + e);
    float m = o2f(g_maxi[d * 2 + h]);
    float a = __expf(g_score[idx] - m);
    g_score[idx] = a;
    atomicAdd(&g_denom[d * 2 + h], a);
}

__global__ void __launch_bounds__(256)
edge_aggr_128(const float* __restrict__ z, const int* __restrict__ src,
              const int* __restrict__ dst, float* __restrict__ out)
{
    int e = blockIdx.x * 8 + (threadIdx.x >> 5);
    if (e >= EE) return;
    int lane = threadIdx.x & 31;
    int s = __ldg(src + e), d = __ldg(dst + e);
    int h = lane >> 4;

    float den = g_denom[d * 2 + h];
    float alpha = g_score[e * 2 + h] / (den == 0.f ? 1.f : den);

    float4 zs = *reinterpret_cast<const float4*>(z + (size_t)s * 128 + lane * 4);
    float* o = out + (size_t)d * 128 + lane * 4;
    atomicAdd(o + 0, zs.x * alpha);
    atomicAdd(o + 1, zs.y * alpha);
    atomicAdd(o + 2, zs.z * alpha);
    atomicAdd(o + 3, zs.w * alpha);
}

// ---------------------------------------------------------------------------
// Final layer (C=16, H=2): one thread per (edge, head)
// ---------------------------------------------------------------------------
__global__ void edge_score_f(const float* __restrict__ z, const int* __restrict__ src,
                             const int* __restrict__ dst, const float* __restrict__ attnf)
{
    int idx = blockIdx.x * blockDim.x + threadIdx.x;
    if (idx >= EE * 2) return;
    int e = idx >> 1, h = idx & 1;
    int s = __ldg(src + e), d = __ldg(dst + e);

    const float4* zs = reinterpret_cast<const float4*>(z + (size_t)s * 32 + h * 16);
    const float4* zd = reinterpret_cast<const float4*>(z + (size_t)d * 32 + h * 16);
    const float4* at = reinterpret_cast<const float4*>(attnf + h * 16);

    float p = 0.f;
#pragma unroll
    for (int q = 0; q < 4; q++) {
        float4 a = zs[q], b = zd[q], w = at[q];
        p += lrelu(a.x + b.x) * w.x;
        p += lrelu(a.y + b.y) * w.y;
        p += lrelu(a.z + b.z) * w.z;
        p += lrelu(a.w + b.w) * w.w;
    }
    g_score[idx] = p;
    atomicMax(&g_maxi[d * 2 + h], f2o(p));
}

__global__ void edge_aggr_f(const float* __restrict__ z, const int* __restrict__ src,
                            const int* __restrict__ dst, float* __restrict__ outf)
{
    int idx = blockIdx.x * blockDim.x + threadIdx.x;
    if (idx >= EE * 2) return;
    int e = idx >> 1, h = idx & 1;
    int s = __ldg(src + e), d = __ldg(dst + e);

    float den = g_denom[d * 2 + h];
    float alpha = g_score[idx] / (den == 0.f ? 1.f : den);

    const float4* zs = reinterpret_cast<const float4*>(z + (size_t)s * 32 + h * 16);
    float* o = outf + (size_t)d * 32 + h * 16;
#pragma unroll
    for (int q = 0; q < 4; q++) {
        float4 v = zs[q];
        atomicAdd(o + q * 4 + 0, v.x * alpha);
        atomicAdd(o + q * 4 + 1, v.y * alpha);
        atomicAdd(o + q * 4 + 2, v.z * alpha);
        atomicAdd(o + q * 4 + 3, v.w * alpha);
    }
}

// Mean over heads + graph pooling (segment_sum by node_graph)
__global__ void pool_k(const float* __restrict__ outf, const int* __restrict__ ng)
{
    int idx = blockIdx.x * blockDim.x + threadIdx.x;
    if (idx >= NN * CC) return;
    int n = idx >> 4, c = idx & 15;
    float v = 0.5f * (outf[n * 32 + c] + outf[n * 32 + 16 + c]);
    atomicAdd(&g_pooled[__ldg(ng + n) * CC + c], v);
}

// ---------------------------------------------------------------------------
// Tiny MLP head: lin -> batchnorm(training stats) -> relu -> lin -> log_softmax
// Single block, 512 threads = (32 graphs x 16 classes).
// ---------------------------------------------------------------------------
__global__ void __launch_bounds__(512)
mlp_k(const float* __restrict__ w1, const float* __restrict__ gamma,
      const float* __restrict__ beta, const float* __restrict__ w2,
      float* __restrict__ out)
{
    __shared__ float P[GG][CC], H1[GG][CC], R[GG][CC], O[GG][CC];
    __shared__ float mu[CC], iv[CC];
    __shared__ float rm[GG], rl[GG];

    int t = threadIdx.x;
    int i = t >> 4, j = t & 15;

    P[i][j] = g_pooled[t];
    __syncthreads();

    float acc = 0.f;
#pragma unroll
    for (int k = 0; k < CC; k++) acc += P[i][k] * w1[k * CC + j];
    H1[i][j] = acc;
    __syncthreads();

    if (t < CC) {
        float m = 0.f;
        for (int r = 0; r < GG; r++) m += H1[r][t];
        m *= (1.f / GG);
        float v = 0.f;
        for (int r = 0; r < GG; r++) { float d = H1[r][t] - m; v += d * d; }
        v *= (1.f / GG);
        mu[t] = m;
        iv[t] = rsqrtf(v + BN_EPS);
    }
    __syncthreads();

    float hn = (H1[i][j] - mu[j]) * iv[j] * gamma[j] + beta[j];
    R[i][j] = fmaxf(hn, 0.f);
    __syncthreads();

    acc = 0.f;
#pragma unroll
    for (int k = 0; k < CC; k++) acc += R[i][k] * w2[k * CC + j];
    O[i][j] = acc;
    __syncthreads();

    if (j == 0) {
        float m = -1e30f;
        for (int k = 0; k < CC; k++) m = fmaxf(m, O[i][k]);
        float s = 0.f;
        for (int k = 0; k < CC; k++) s += __expf(O[i][k] - m);
        rm[i] = m;
        rl[i] = logf(s);
    }
    __syncthreads();

    out[t] = O[i][j] - rm[i] - rl[i];
}

// ---------------------------------------------------------------------------
// Host launch sequence (graph-capturable; kernel launches only)
// ---------------------------------------------------------------------------
extern "C" void kernel_launch(void* const* d_in, const int* in_sizes, int n_in,
                              void* d_out, int out_size)
{
    const float* feat  = (const float*)d_in[0];
    const float* W0    = (const float*)d_in[1];
    const float* attn0 = (const float*)d_in[2];
    const float* W1    = (const float*)d_in[3];
    const float* attn1 = (const float*)d_in[4];
    const float* W2    = (const float*)d_in[5];
    const float* attn2 = (const float*)d_in[6];
    const float* Wf    = (const float*)d_in[7];
    const float* attnf = (const float*)d_in[8];
    const float* mw1   = (const float*)d_in[9];
    const float* gam   = (const float*)d_in[10];
    const float* bet   = (const float*)d_in[11];
    const float* mw2   = (const float*)d_in[12];
    const int*   src   = (const int*)d_in[13];
    const int*   dst   = (const int*)d_in[14];
    const int*   ng    = (const int*)d_in[15];

    float *buf0, *buf1, *zbuf, *outf;
    cudaGetSymbolAddress((void**)&buf0, g_buf0);
    cudaGetSymbolAddress((void**)&buf1, g_buf1);
    cudaGetSymbolAddress((void**)&zbuf, g_z);
    cudaGetSymbolAddress((void**)&outf, g_outf);

    const int GEMM_BLOCKS = (NN + 127) / 128;          // 391
    const int EW_BLOCKS   = (EE + 7) / 8;              // warp-per-edge: 100000
    const int ET_BLOCKS   = (EE * 2 + 255) / 256;      // thread-per-(edge,head): 6250
    const int INIT_BLOCKS = (NN * 128 + 255) / 256;    // 25000
    const int INITF_BLOCKS= (NN * 32 + 255) / 256;     // 6250 (covers NN*2 too)
    const int POOL_BLOCKS = (NN * CC + 255) / 256;     // 3125

    // ---- layer 0: feat -> buf0
    gemm_k128<128, 8><<<GEMM_BLOCKS, 256>>>(feat, W0, zbuf, NN, 0);
    init_k<<<INIT_BLOCKS, 256>>>(buf0, NN * 128, 0);
    edge_score_128<<<EW_BLOCKS, 256>>>(zbuf, src, dst, attn0);
    edge_exp<<<ET_BLOCKS, 256>>>(dst);
    edge_aggr_128<<<EW_BLOCKS, 256>>>(zbuf, src, dst, buf0);

    // ---- layer 1: relu(buf0) -> buf1
    gemm_k128<128, 8><<<GEMM_BLOCKS, 256>>>(buf0, W1, zbuf, NN, 1);
    init_k<<<INIT_BLOCKS, 256>>>(buf1, NN * 128, 0);
    edge_score_128<<<EW_BLOCKS, 256>>>(zbuf, src, dst, attn1);
    edge_exp<<<ET_BLOCKS, 256>>>(dst);
    edge_aggr_128<<<EW_BLOCKS, 256>>>(zbuf, src, dst, buf1);

    // ---- layer 2: relu(buf1) -> buf0
    gemm_k128<128, 8><<<GEMM_BLOCKS, 256>>>(buf1, W2, zbuf, NN, 1);
    init_k<<<INIT_BLOCKS, 256>>>(buf0, NN * 128, 0);
    edge_score_128<<<EW_BLOCKS, 256>>>(zbuf, src, dst, attn2);
    edge_exp<<<ET_BLOCKS, 256>>>(dst);
    edge_aggr_128<<<EW_BLOCKS, 256>>>(zbuf, src, dst, buf0);

    // ---- final GAT layer: relu(buf0) @ Wf -> zf [N,32]; aggregate -> outf
    gemm_k128<32, 2><<<GEMM_BLOCKS, 256>>>(buf0, Wf, zbuf, NN, 1);
    init_k<<<INITF_BLOCKS, 256>>>(outf, NN * 32, 1);
    edge_score_f<<<ET_BLOCKS, 256>>>(zbuf, src, dst, attnf);
    edge_exp<<<ET_BLOCKS, 256>>>(dst);
    edge_aggr_f<<<ET_BLOCKS, 256>>>(zbuf, src, dst, outf);

    // ---- head: mean over heads, graph pooling, MLP+BN+log_softmax
    pool_k<<<POOL_BLOCKS, 256>>>(outf, ng);
    mlp_k<<<1, 512>>>(mw1, gam, bet, mw2, (float*)d_out);

    (void)in_sizes; (void)n_in; (void)out_size;
}